// round 6
// baseline (speedup 1.0000x reference)
#include <cuda_runtime.h>
#include <cuda_bf16.h>

#define N_RELS 64
#define REL_STRIDE4 3      // 3 float4 per relation record = 48B
#define REP_STRIDE4 193    // replica stride in float4: 3088B == 16B (mod 128B)
#define N_REP 8            // one replica per 16B bank-group

// Sparsemax for d=3 via closed-form threshold:
//   tau = max_k (cs_k - 1)/k  == reference's (cs[ksup-1]-1)/ksup
// (support at k+1 <=> (cs_{k+1}-1)/(k+1) > (cs_k-1)/k, support prefix-closed).
static __device__ __forceinline__ void sparsemax3(float x0, float x1, float x2,
                                                  float &o0, float &o1, float &o2) {
    float mx  = fmaxf(fmaxf(x0, x1), x2);
    float mn  = fminf(fminf(x0, x1), x2);
    float sum = x0 + x1 + x2;
    float t1 = mx - 1.0f;
    float t2 = (sum - mn - 1.0f) * 0.5f;
    float t3 = (sum - 1.0f) * (1.0f / 3.0f);
    float tau = fmaxf(t1, fmaxf(t2, t3));
    o0 = fmaxf(x0 - tau, 0.0f);
    o1 = fmaxf(x1 - tau, 0.0f);
    o2 = fmaxf(x2 - tau, 0.0f);
}

static __device__ __forceinline__ void row_compute(
    float p0, float p1, float p2,
    float h0, float h1, float h2,
    const float4 *__restrict__ relp,
    float zeps, float sf,
    float &a0, float &a1, float &a2)
{
    float4 m0 = relp[0];   // {M00,M01,M02, beta0}
    float4 m1 = relp[1];   // {M10,M11,M12, beta1}
    float4 m2 = relp[2];   // {M20,M21,M22, beta2}

    // c = M[rel] @ child
    float c0 = m0.x * h0 + m0.y * h1 + m0.z * h2;
    float c1 = m1.x * h0 + m1.y * h1 + m1.z * h2;
    float c2 = m2.x * h0 + m2.y * h1 + m2.z * h2;
    sparsemax3(c0, c1, c2, c0, c1, c2);
    // (second sparsemax is an exact identity on a simplex point — dropped)
    sparsemax3(p0, p1, p2, p0, p1, p2);

    // alpha = (1-b)*p + b*c == p + b*(c-p)
    a0 = p0 + m0.w * (c0 - p0);
    a1 = p1 + m1.w * (c1 - p1);
    a2 = p2 + m2.w * (c2 - p2);

    // entropy of clamped normalized mixture (base-2; ln2 folded into divide)
    float w0 = fmaxf(p0 + c0, zeps);
    float w1 = fmaxf(p1 + c1, zeps);
    float w2 = fmaxf(p2 + c2, zeps);
    float inv = __fdividef(1.0f, w0 + w1 + w2);
    w0 *= inv; w1 *= inv; w2 *= inv;
    float t2 = w0 * __log2f(w0) + w1 * __log2f(w1) + w2 * __log2f(w2); // < 0

    // sparsemax outputs sum to 1 => max comp >= 1/3 => pp*cc >= 1/81:
    // reference's max(nrm,1e-10) guard is provably inactive.
    float dot = p0 * c0 + p1 * c1 + p2 * c2;
    float pp  = p0 * p0 + p1 * p1 + p2 * p2;
    float cc  = c0 * c0 + c1 * c1 + c2 * c2;
    float rq  = rsqrtf(pp * cc);
    float cosv = 0.1f + dot * rq;
    float scale = __fdividef(sf * cosv, -0.69314718056f * t2);

    a0 = fmaxf(a0 * scale, 0.001f);
    a1 = fmaxf(a1 * scale, 0.001f);
    a2 = fmaxf(a2 * scale, 0.001f);
}

// Compute one quad (4 rows) from preloaded registers.
static __device__ __forceinline__ void quad_compute(
    const float4 pA, const float4 pB, const float4 pC,
    const float4 cA, const float4 cB, const float4 cC,
    const int4 r4, const float4 *__restrict__ relBase,
    float zeps, float sf, float4 &oA, float4 &oB, float4 &oC)
{
    float pv[12] = {pA.x, pA.y, pA.z, pA.w, pB.x, pB.y, pB.z, pB.w,
                    pC.x, pC.y, pC.z, pC.w};
    float cv[12] = {cA.x, cA.y, cA.z, cA.w, cB.x, cB.y, cB.z, cB.w,
                    cC.x, cC.y, cC.z, cC.w};
    int rr[4] = {r4.x, r4.y, r4.z, r4.w};
    float ov[12];
#pragma unroll
    for (int i = 0; i < 4; i++) {
        row_compute(pv[3 * i], pv[3 * i + 1], pv[3 * i + 2],
                    cv[3 * i], cv[3 * i + 1], cv[3 * i + 2],
                    relBase + rr[i] * REL_STRIDE4, zeps, sf,
                    ov[3 * i], ov[3 * i + 1], ov[3 * i + 2]);
    }
    oA = make_float4(ov[0], ov[1], ov[2],  ov[3]);
    oB = make_float4(ov[4], ov[5], ov[6],  ov[7]);
    oC = make_float4(ov[8], ov[9], ov[10], ov[11]);
}

__global__ void __launch_bounds__(256, 4)
alpha_kernel(const float *__restrict__ prnt,
             const float *__restrict__ child,
             const float *__restrict__ Mg,
             const float *__restrict__ betag,
             const float *__restrict__ zeps_p,
             const float *__restrict__ sf_p,
             const int *__restrict__ rels,
             float *__restrict__ out,
             int n, int nquads, int half)
{
    // 8 replicas of the rel table, replica k at float4-offset k*193.
    // 193 mod 8 == 1  =>  16B-chunk index mod 8 = k + 3*rel + slot.
    // Lane l reads replica (l&7): within any LDS.128 quarter-warp phase the
    // 8 lanes hit 8 DISTINCT bank-groups regardless of rel -> conflict-free.
    __shared__ float4 sRel[N_REP * REP_STRIDE4];
    {
        float *sF = reinterpret_cast<float *>(sRel);
        // 768 floats per replica, 8 replicas: 6144 writes / 256 thr = 24 each
        for (int i = threadIdx.x; i < N_RELS * 12; i += blockDim.x) {
            int r = i / 12, j = i % 12;
            int row = j >> 2, c = j & 3;
            float v = (c < 3) ? Mg[r * 9 + row * 3 + c] : betag[r * 3 + row];
#pragma unroll
            for (int k = 0; k < N_REP; k++)
                sF[k * (REP_STRIDE4 * 4) + r * 12 + j] = v;
        }
    }
    __syncthreads();

    const float4 *myRel = &sRel[(threadIdx.x & 7) * REP_STRIDE4];

    const float zeps = __ldg(zeps_p);
    const float sf   = __ldg(sf_p);

    int idx = blockIdx.x * blockDim.x + threadIdx.x;
    const float4 *pr4 = reinterpret_cast<const float4 *>(prnt);
    const float4 *ch4 = reinterpret_cast<const float4 *>(child);
    const int4  *rl4  = reinterpret_cast<const int4 *>(rels);
    float4 *o4 = reinterpret_cast<float4 *>(out);

    int qa = idx;               // first quad
    int qb = half + idx;        // second quad (warp-coalesced group)
    bool da = qa < half;
    bool db = qb < nquads;

    // ---- front-batch ALL global loads (max MLP) ----
    float4 paA, paB, paC, caA, caB, caC; int4 raQ;
    float4 pbA, pbB, pbC, cbA, cbB, cbC; int4 rbQ;
    if (da) {
        size_t o = (size_t)qa * 3;
        paA = __ldcs(pr4 + o);     paB = __ldcs(pr4 + o + 1); paC = __ldcs(pr4 + o + 2);
        caA = __ldcs(ch4 + o);     caB = __ldcs(ch4 + o + 1); caC = __ldcs(ch4 + o + 2);
        raQ = __ldcs(rl4 + qa);
    }
    if (db) {
        size_t o = (size_t)qb * 3;
        pbA = __ldcs(pr4 + o);     pbB = __ldcs(pr4 + o + 1); pbC = __ldcs(pr4 + o + 2);
        cbA = __ldcs(ch4 + o);     cbB = __ldcs(ch4 + o + 1); cbC = __ldcs(ch4 + o + 2);
        rbQ = __ldcs(rl4 + qb);
    }

    if (da) {
        float4 oA, oB, oC;
        quad_compute(paA, paB, paC, caA, caB, caC, raQ, myRel, zeps, sf, oA, oB, oC);
        size_t o = (size_t)qa * 3;
        __stcs(o4 + o, oA); __stcs(o4 + o + 1, oB); __stcs(o4 + o + 2, oC);
    }
    if (db) {
        float4 oA, oB, oC;
        quad_compute(pbA, pbB, pbC, cbA, cbB, cbC, rbQ, myRel, zeps, sf, oA, oB, oC);
        size_t o = (size_t)qb * 3;
        __stcs(o4 + o, oA); __stcs(o4 + o + 1, oB); __stcs(o4 + o + 2, oC);
    }

    // scalar tail (n % 4 rows) — empty for N = 8,000,000 but kept general
    int rem = n - nquads * 4;
    if (idx < rem) {
        int i = nquads * 4 + idx;
        float a0, a1, a2;
        row_compute(prnt[3 * i], prnt[3 * i + 1], prnt[3 * i + 2],
                    child[3 * i], child[3 * i + 1], child[3 * i + 2],
                    myRel + rels[i] * REL_STRIDE4, zeps, sf, a0, a1, a2);
        out[3 * i] = a0; out[3 * i + 1] = a1; out[3 * i + 2] = a2;
    }
}

extern "C" void kernel_launch(void* const* d_in, const int* in_sizes, int n_in,
                              void* d_out, int out_size) {
    // metadata order: prnt_probs, child_probs, M, beta, z_epsilon, scale_factor, rels, var_sfx
    const float *prnt  = (const float *)d_in[0];
    const float *child = (const float *)d_in[1];
    const float *Mg    = (const float *)d_in[2];
    const float *betag = (const float *)d_in[3];
    const float *zeps  = (const float *)d_in[4];
    const float *sf    = (const float *)d_in[5];
    const int   *rels  = (const int *)d_in[6];
    float *out = (float *)d_out;

    int n = in_sizes[6];
    int nquads = n / 4;
    int half = (nquads + 1) / 2;
    int work = half > 0 ? half : 1;
    int threads = 256;
    int blocks = (work + threads - 1) / threads;

    alpha_kernel<<<blocks, threads>>>(prnt, child, Mg, betag, zeps, sf, rels,
                                      out, n, nquads, half);
}